// round 16
// baseline (speedup 1.0000x reference)
#include <cuda_runtime.h>

#define BB 2
#define LL 1024
#define DD 64
#define NROWS (BB*LL)
#define NB (NROWS*DD)
#define SCALE 0.35355339059327373f
#define LOG2E 1.4426950408889634f
#define SCALE2 (SCALE * LOG2E)

// persistent activations (no allocation allowed)
__device__ float g_qvs[NB];
__device__ float g_kvs[NB];
// double-buffered projections: block i reads buf (i&1), epilogue writes (i+1)&1
__device__ float g_q1[2*NB];
__device__ float g_q2[2*NB];
__device__ float g_kk[2*NB];
__device__ float g_vv[2*NB];

// precomputed squared distances, tiled to match attn staging:
// [side][b][qtile(128)][ktile(16)][qi(8)*64 + k(64)]  = 16 MB
__device__ float g_dist[2][BB][128][16][512];

// piecewise-linear distance-bias tables (per block), pre-scaled by log2(e)
__device__ float g_pl_t[6][16];
__device__ float g_pl_AC[6][17][16];
__device__ int   g_pl_i0[6];

__device__ __forceinline__ float ex2f(float x) {
    float r; asm("ex2.approx.f32 %0, %1;" : "=f"(r) : "f"(x)); return r;
}
__device__ __forceinline__ unsigned smem_u32(const void* p) {
    return (unsigned)__cvta_generic_to_shared(p);
}
__device__ __forceinline__ void cpa16(unsigned dst, const void* src) {
    asm volatile("cp.async.cg.shared.global [%0], [%1], 16;" :: "r"(dst), "l"(src));
}

// ---------------------------------------------------------------------------
// Setup: fold dist-bias MLP into 17-interval piecewise-linear form (x log2e).
// ---------------------------------------------------------------------------
__global__ void bias_setup_kernel(
    const float* __restrict__ bw1, const float* __restrict__ bb1,
    const float* __restrict__ bw2, const float* __restrict__ bb2)
{
    int i = blockIdx.x;
    if (threadIdx.x != 0) return;
    float w1[16], b1[16], t[16];
    for (int j = 0; j < 16; ++j) {
        w1[j] = bw1[i*16 + j];
        b1[j] = bb1[i*16 + j];
        t[j]  = (w1[j] != 0.f) ? (-b1[j] / w1[j]) : -1e30f;
    }
    int ord[16];
    for (int j = 0; j < 16; ++j) ord[j] = j;
    for (int a = 1; a < 16; ++a) {
        int o = ord[a]; float tv = t[o]; int b = a - 1;
        while (b >= 0 && t[ord[b]] > tv) { ord[b+1] = ord[b]; --b; }
        ord[b+1] = o;
    }
    int i0 = 0;
    for (int j = 0; j < 16; ++j) {
        g_pl_t[i][j] = t[ord[j]];
        if (t[ord[j]] <= 0.f) ++i0;
    }
    g_pl_i0[i] = i0;
    for (int m = 0; m <= 16; ++m) {
        float A[8], C[8];
        for (int h = 0; h < 8; ++h) { A[h] = 0.f; C[h] = 0.f; }
        for (int a = 0; a < 16; ++a) {
            int j = ord[a];
            bool act;
            if (w1[j] > 0.f)      act = (a < m);
            else if (w1[j] < 0.f) act = (a >= m);
            else                  act = (b1[j] > 0.f);
            if (act) {
                for (int h = 0; h < 8; ++h) {
                    A[h] += w1[j] * bw2[i*128 + j*8 + h];
                    C[h] += b1[j] * bw2[i*128 + j*8 + h];
                }
            }
        }
        for (int h = 0; h < 8; ++h) {
            g_pl_AC[i][m][h]     = A[h] * LOG2E;
            g_pl_AC[i][m][8 + h] = (C[h] + bb2[i*8 + h]) * LOG2E;
        }
    }
}

// ---------------------------------------------------------------------------
// Distance precompute: d(q,k) once, reused across all 6 blocks.
// ---------------------------------------------------------------------------
__global__ __launch_bounds__(256) void dist_kernel(
    const float* __restrict__ s_test, const float* __restrict__ s_ctx)
{
    __shared__ float2 sq[8];
    int tid = threadIdx.x;
    int qt = blockIdx.x, b = blockIdx.y, side = blockIdx.z;
    const float2* qc = (const float2*)(side ? s_ctx : s_test) + b*LL + qt*8;
    const float2* kc = (const float2*)s_ctx + b*LL;
    if (tid < 8) sq[tid] = qc[tid];
    __syncthreads();
    int qi = tid >> 5, lane = tid & 31;
    float qx = sq[qi].x, qy = sq[qi].y;
    float* D = &g_dist[side][b][qt][0][0];
#pragma unroll 4
    for (int kt = 0; kt < 16; ++kt) {
#pragma unroll
        for (int kk = 0; kk < 2; ++kk) {
            int k = kt*64 + kk*32 + lane;
            float2 c = kc[k];
            float dx = qx - c.x, dy = qy - c.y;
            D[kt*512 + qi*64 + kk*32 + lane] = fmaf(dx, dx, dy*dy);
        }
    }
}

// ---------------------------------------------------------------------------
// Embed: 4 rows/CTA + fused block-0 projections (written to buffer 0).
// ---------------------------------------------------------------------------
__global__ __launch_bounds__(256) void embed_kernel(
    const float* __restrict__ s_ctx, const float* __restrict__ f_ctx,
    const float* __restrict__ s_test, const float* __restrict__ table,
    const float* __restrict__ w1, const float* __restrict__ b1,
    const float* __restrict__ w2, const float* __restrict__ b2,
    const float* __restrict__ wq, const float* __restrict__ bq,
    const float* __restrict__ wk, const float* __restrict__ bk,
    const float* __restrict__ wv, const float* __restrict__ bv)
{
    __shared__ float xs[4][8];
    __shared__ float h4[4][256];
    __shared__ float part[4][256];
    __shared__ float sy[4][64];
    int tid = threadIdx.x;
    int row0 = blockIdx.x * 4;
    int sideq = row0 >> 11;
    if (tid < 32) {
        int r = tid >> 3, i = tid & 7;
        if (i < 7) {
            int row = (row0 + r) & 2047;
            int b = row >> 10, pos = row & 1023;
            float v;
            if (sideq == 0) {
                v = (i < 4) ? table[4 + i]
                  : (i < 6) ? s_ctx[(b*LL + pos)*2 + i - 4]
                            : f_ctx[b*LL + pos];
            } else {
                v = (i < 4) ? table[i]
                  : (i < 6) ? s_test[(b*LL + pos)*2 + i - 4]
                            : 0.f;
            }
            xs[r][i] = v;
        }
    }
    __syncthreads();
    float b1v = b1[tid];
    float a0 = b1v, a1 = b1v, a2 = b1v, a3 = b1v;
#pragma unroll
    for (int i = 0; i < 7; ++i) {
        float w = w1[i*256 + tid];
        a0 = fmaf(xs[0][i], w, a0);
        a1 = fmaf(xs[1][i], w, a1);
        a2 = fmaf(xs[2][i], w, a2);
        a3 = fmaf(xs[3][i], w, a3);
    }
    h4[0][tid] = fmaxf(a0, 0.f); h4[1][tid] = fmaxf(a1, 0.f);
    h4[2][tid] = fmaxf(a2, 0.f); h4[3][tid] = fmaxf(a3, 0.f);
    __syncthreads();
    int oc = tid & 63, g = tid >> 6;
    float p0 = 0.f, p1 = 0.f, p2 = 0.f, p3 = 0.f;
#pragma unroll 8
    for (int j = g*64; j < g*64 + 64; ++j) {
        float w = w2[j*64 + oc];
        p0 = fmaf(h4[0][j], w, p0);
        p1 = fmaf(h4[1][j], w, p1);
        p2 = fmaf(h4[2][j], w, p2);
        p3 = fmaf(h4[3][j], w, p3);
    }
    part[0][tid] = p0; part[1][tid] = p1; part[2][tid] = p2; part[3][tid] = p3;
    __syncthreads();
    {
        int r = tid >> 6, col = tid & 63;
        float v = part[r][col] + part[r][64 + col] + part[r][128 + col]
                + part[r][192 + col] + b2[col];
        int rr = (row0 + r) & 2047;
        float* dst = sideq ? g_qvs : g_kvs;
        dst[rr*64 + col] = v;
        sy[r][col] = v;
    }
    __syncthreads();

    // fused block-0 projections (buffer 0)
    {
        int r = tid >> 6, c = tid & 63;
        int rr = (row0 + r) & 2047;
        const float* Wm[3]; const float* Bm[3]; float* Dm[3]; int nmat;
        if (sideq == 0) {
            nmat = 3;
            Wm[0] = wq; Bm[0] = bq; Dm[0] = g_q2;
            Wm[1] = wk; Bm[1] = bk; Dm[1] = g_kk;
            Wm[2] = wv; Bm[2] = bv; Dm[2] = g_vv;
        } else {
            nmat = 1;
            Wm[0] = wq; Bm[0] = bq; Dm[0] = g_q1;
        }
        for (int mm = 0; mm < nmat; ++mm) {
            const float* W = Wm[mm];
            float pa = Bm[mm][c];
#pragma unroll 16
            for (int k = 0; k < 64; ++k)
                pa = fmaf(sy[r][k], W[k*64 + c], pa);
            Dm[mm][rr*64 + c] = pa;
        }
    }
}

// ---------------------------------------------------------------------------
// MEGA attention block: biased attention + out-proj + residual + LN
// + FFN + residual + LN + NEXT-BLOCK projections, all fused.
// grid (128, B, 2). CTA = 8 warps = 8 queries, warp w = head w.
// Reads Q/K/V from buffer (iblk&1); writes next-block proj to (iblk+1)&1
// (double buffering removes the intra-launch mainloop/epilogue race).
// ---------------------------------------------------------------------------
__global__ __launch_bounds__(256, 2) void attn_kernel(
    int iblk,
    const float* __restrict__ wo, const float* __restrict__ bo,
    const float* __restrict__ ns, const float* __restrict__ nb,
    const float* __restrict__ fw1, const float* __restrict__ fb1,
    const float* __restrict__ fw2, const float* __restrict__ fb2,
    const float* __restrict__ wq, const float* __restrict__ bq,
    const float* __restrict__ wk, const float* __restrict__ bk,
    const float* __restrict__ wv, const float* __restrict__ bv)
{
    // dynamic: K0[1024] V0[1024] K1[1024] V1[1024] float4 (64KB)
    extern __shared__ float4 dyn[];

    __shared__ float  sQ[512];       // 8 queries x 64, pre-scaled
    __shared__ float  sDbuf[2][512]; // double-buffered distance tiles
    __shared__ float  sAC[272];      // PL tables
    __shared__ float  sO[512];
    __shared__ float  sy[8][64];     // LN'd attention rows / ffn rows
    __shared__ float  shm[8][128];   // ffn hidden
    __shared__ float  sRed[8][2][2];

    const int tid = threadIdx.x, wid = tid >> 5, lane = tid & 31;
    const int side = blockIdx.z, b = blockIdx.y;
    const int buf = (iblk & 1) * NB;

    const float* Qp = (side ? g_q2 : g_q1) + buf;

    for (int n = tid; n < 272; n += 256)
        sAC[n] = ((const float*)g_pl_AC)[iblk*272 + n];
    sQ[tid]       = Qp[(b*LL + blockIdx.x*8)*64 + tid] * SCALE2;
    sQ[256 + tid] = Qp[(b*LL + blockIdx.x*8)*64 + 256 + tid] * SCALE2;

    const int i0 = g_pl_i0[iblk];
    const float* trg = g_pl_t[iblk];

    float l[8];
#pragma unroll
    for (int i = 0; i < 8; ++i) l[i] = 0.f;
    float o[64];
#pragma unroll
    for (int d = 0; d < 64; ++d) o[d] = 0.f;

    const int ksw = lane & 15, kb0 = lane << 4;
    const int ikk0 = kb0 + ((2*wid)     ^ ksw);
    const int ikk1 = kb0 + ((2*wid + 1) ^ ksw);

    const float4* Kg = (const float4*)(g_kk + buf + b*LL*64);
    const float4* Vg = (const float4*)(g_vv + buf + b*LL*64);
    const float4* Dg = (const float4*)&g_dist[side][b][blockIdx.x][0][0];

    int sgN[4]; unsigned sgU[4];
#pragma unroll
    for (int n4 = 0; n4 < 4; ++n4) {
        int n = n4*256 + tid;
        int kr = n >> 4, c = n & 15;
        sgN[n4] = n;
        sgU[n4] = (unsigned)(((kr << 4) + (c ^ (kr & 15))) * 16);
    }
    const unsigned uK0 = smem_u32(dyn);
    const unsigned uV0 = uK0 + 16384;
    const unsigned uK1 = uK0 + 32768;
    const unsigned uV1 = uK0 + 49152;
    const unsigned uD0 = smem_u32(sDbuf);
    const unsigned uD1 = uD0 + 2048;

    __syncthreads();   // sQ / sAC visible
    const float A16 = sAC[256 + wid];
    const float C16 = sAC[264 + wid];
    const float4* sQ4 = (const float4*)sQ;

    // prologue: stage tile 0 into buffer 0 (K, V, D)
#pragma unroll
    for (int n4 = 0; n4 < 4; ++n4) {
        cpa16(uK0 + sgU[n4], Kg + sgN[n4]);
        cpa16(uV0 + sgU[n4], Vg + sgN[n4]);
    }
    if (tid < 128) cpa16(uD0 + tid*16, Dg + tid);
    asm volatile("cp.async.commit_group;");

    for (int t = 0; t < 16; ++t) {
        const int bf = t & 1;
        asm volatile("cp.async.wait_group 0;");
        __syncthreads();

        if (t + 1 < 16) {
            const unsigned uK = bf ? uK0 : uK1;
            const unsigned uV = bf ? uV0 : uV1;
            const unsigned uD = bf ? uD0 : uD1;
#pragma unroll
            for (int n4 = 0; n4 < 4; ++n4) {
                cpa16(uK + sgU[n4], Kg + (t+1)*1024 + sgN[n4]);
                cpa16(uV + sgU[n4], Vg + (t+1)*1024 + sgN[n4]);
            }
            if (tid < 128) cpa16(uD + tid*16, Dg + (t+1)*128 + tid);
            asm volatile("cp.async.commit_group;");
        }

        const float4* sK = bf ? (dyn + 2048) : dyn;
        const float4* sV = bf ? (dyn + 3072) : (dyn + 1024);
        const float*  sD = sDbuf[bf];

        float s[16];
        if (i0 == 16) {
#pragma unroll
            for (int qi = 0; qi < 8; ++qi) {
                float dq0 = sD[qi*64 + lane];
                float dq1 = sD[qi*64 + 32 + lane];
                s[qi*2+0] = fmaf(A16, dq0, C16);
                s[qi*2+1] = fmaf(A16, dq1, C16);
            }
        } else {
#pragma unroll
            for (int qi = 0; qi < 8; ++qi) {
                float dq0 = sD[qi*64 + lane];
                float dq1 = sD[qi*64 + 32 + lane];
                int m0 = i0, m1 = i0;
                for (int i = i0; i < 16; ++i) {
                    float tv = trg[i];
                    m0 += dq0 > tv; m1 += dq1 > tv;
                }
                s[qi*2+0] = fmaf(sAC[m0*16 + wid], dq0, sAC[m0*16 + 8 + wid]);
                s[qi*2+1] = fmaf(sAC[m1*16 + wid], dq1, sAC[m1*16 + 8 + wid]);
            }
        }

#pragma unroll
        for (int cc = 0; cc < 2; ++cc) {
            const int ik = cc ? ikk1 : ikk0;
            float4 k0 = sK[ik];
            float4 k1 = sK[ik + 512];
#pragma unroll
            for (int qi = 0; qi < 8; ++qi) {
                float4 qv = sQ4[qi*16 + 2*wid + cc];
                s[qi*2]   = fmaf(qv.x, k0.x, s[qi*2]);
                s[qi*2]   = fmaf(qv.y, k0.y, s[qi*2]);
                s[qi*2]   = fmaf(qv.z, k0.z, s[qi*2]);
                s[qi*2]   = fmaf(qv.w, k0.w, s[qi*2]);
                s[qi*2+1] = fmaf(qv.x, k1.x, s[qi*2+1]);
                s[qi*2+1] = fmaf(qv.y, k1.y, s[qi*2+1]);
                s[qi*2+1] = fmaf(qv.z, k1.z, s[qi*2+1]);
                s[qi*2+1] = fmaf(qv.w, k1.w, s[qi*2+1]);
            }
        }

#pragma unroll
        for (int i = 0; i < 16; ++i) s[i] = ex2f(s[i]);
#pragma unroll
        for (int qi = 0; qi < 8; ++qi) l[qi] += s[qi*2] + s[qi*2+1];

#pragma unroll
        for (int cc = 0; cc < 2; ++cc) {
            const int ik = cc ? ikk1 : ikk0;
            float4 v0 = sV[ik];
            float4 v1 = sV[ik + 512];
#pragma unroll
            for (int qi = 0; qi < 8; ++qi) {
                const int ob = qi*8 + cc*4;
                float pa = s[qi*2], pb = s[qi*2+1];
                o[ob+0] = fmaf(pa, v0.x, o[ob+0]);
                o[ob+0] = fmaf(pb, v1.x, o[ob+0]);
                o[ob+1] = fmaf(pa, v0.y, o[ob+1]);
                o[ob+1] = fmaf(pb, v1.y, o[ob+1]);
                o[ob+2] = fmaf(pa, v0.z, o[ob+2]);
                o[ob+2] = fmaf(pb, v1.z, o[ob+2]);
                o[ob+3] = fmaf(pa, v0.w, o[ob+3]);
                o[ob+3] = fmaf(pb, v1.w, o[ob+3]);
            }
        }
    }

    // merge lanes (butterfly)
#pragma unroll
    for (int i = 0; i < 8; ++i) {
        float lh = l[i];
#pragma unroll
        for (int off = 16; off; off >>= 1)
            lh += __shfl_xor_sync(0xffffffffu, lh, off);
        l[i] = 1.f / lh;
    }
#pragma unroll
    for (int d = 0; d < 64; ++d) {
        float v = o[d];
#pragma unroll
        for (int off = 16; off; off >>= 1)
            v += __shfl_xor_sync(0xffffffffu, v, off);
        o[d] = v * l[d >> 3];
    }

    float mv0 = 0.f, mv1 = 0.f;
#pragma unroll
    for (int i = 0; i < 32; ++i)
        if (lane == i) { mv0 = o[i]; mv1 = o[32 + i]; }

    __syncthreads();
    sO[(lane >> 3)*64       + wid*8 + (lane & 7)] = mv0;
    sO[(4 + (lane >> 3))*64 + wid*8 + (lane & 7)] = mv1;
    float* sWo = (float*)dyn;
    const float* Wog = wo + iblk*4096;
    for (int n = tid; n < 4096; n += 256) sWo[n] = Wog[n];
    __syncthreads();

    // ---- out-proj + residual + LN1 ----
    const int c = tid & 63, qA = tid >> 6, qB = qA + 4;
    const int rowA = b*LL + blockIdx.x*8 + qA;
    const int rowB = rowA + 4;
    float accA = bo[iblk*64 + c], accB = accA;
#pragma unroll 16
    for (int i = 0; i < 64; ++i) {
        float w = sWo[i*64 + c];
        accA = fmaf(sO[qA*64 + i], w, accA);
        accB = fmaf(sO[qB*64 + i], w, accB);
    }
    const float* src = side ? g_kvs : g_qvs;
    accA += src[rowA*64 + c];
    accB += src[rowB*64 + c];

    const float nsv = ns[iblk*64 + c], nbv = nb[iblk*64 + c];
    const int half = (tid >> 5) & 1;
    {
        float s1A = accA, s2A = accA*accA, s1B = accB, s2B = accB*accB;
#pragma unroll
        for (int off = 16; off; off >>= 1) {
            s1A += __shfl_xor_sync(0xffffffffu, s1A, off);
            s2A += __shfl_xor_sync(0xffffffffu, s2A, off);
            s1B += __shfl_xor_sync(0xffffffffu, s1B, off);
            s2B += __shfl_xor_sync(0xffffffffu, s2B, off);
        }
        if (lane == 0) {
            sRed[qA][half][0] = s1A; sRed[qA][half][1] = s2A;
            sRed[qB][half][0] = s1B; sRed[qB][half][1] = s2B;
        }
    }
    __syncthreads();
    {
        float tot  = sRed[qA][0][0] + sRed[qA][1][0];
        float tot2 = sRed[qA][0][1] + sRed[qA][1][1];
        float mu = tot * (1.f/64.f);
        float var = tot2 * (1.f/64.f) - mu*mu;
        sy[qA][c] = (accA - mu) * rsqrtf(var + 1e-6f) * nsv + nbv;
    }
    {
        float tot  = sRed[qB][0][0] + sRed[qB][1][0];
        float tot2 = sRed[qB][0][1] + sRed[qB][1][1];
        float mu = tot * (1.f/64.f);
        float var = tot2 * (1.f/64.f) - mu*mu;
        sy[qB][c] = (accB - mu) * rsqrtf(var + 1e-6f) * nsv + nbv;
    }
    __syncthreads();

    // ---- FFN layer 1 (weights via LDG, 4-row reuse) ----
    {
        int h = tid & 127, rg = tid >> 7;
        const float* W1g = fw1 + iblk*8192;
        float b1v = fb1[iblk*128 + h];
        float a4[4];
#pragma unroll
        for (int r = 0; r < 4; ++r) a4[r] = b1v;
#pragma unroll 16
        for (int k = 0; k < 64; ++k) {
            float w = W1g[k*128 + h];
#pragma unroll
            for (int r = 0; r < 4; ++r) a4[r] = fmaf(sy[rg*4 + r][k], w, a4[r]);
        }
#pragma unroll
        for (int r = 0; r < 4; ++r) shm[rg*4 + r][h] = fmaxf(a4[r], 0.f);
    }
    __syncthreads();

    // ---- FFN layer 2 + residual + LN2 ----
    const float* W2g = fw2 + iblk*8192;
    float a2A = fb2[iblk*64 + c], a2B = a2A;
#pragma unroll 16
    for (int k = 0; k < 128; ++k) {
        float w = W2g[k*64 + c];
        a2A = fmaf(shm[qA][k], w, a2A);
        a2B = fmaf(shm[qB][k], w, a2B);
    }
    a2A += sy[qA][c];
    a2B += sy[qB][c];
    {
        float s1A = a2A, s2A = a2A*a2A, s1B = a2B, s2B = a2B*a2B;
#pragma unroll
        for (int off = 16; off; off >>= 1) {
            s1A += __shfl_xor_sync(0xffffffffu, s1A, off);
            s2A += __shfl_xor_sync(0xffffffffu, s2A, off);
            s1B += __shfl_xor_sync(0xffffffffu, s1B, off);
            s2B += __shfl_xor_sync(0xffffffffu, s2B, off);
        }
        if (lane == 0) {
            sRed[qA][half][0] = s1A; sRed[qA][half][1] = s2A;
            sRed[qB][half][0] = s1B; sRed[qB][half][1] = s2B;
        }
    }
    __syncthreads();
    float* dstf = side ? g_kvs : g_qvs;
    float zA, zB;
    {
        float tot  = sRed[qA][0][0] + sRed[qA][1][0];
        float tot2 = sRed[qA][0][1] + sRed[qA][1][1];
        float mu = tot * (1.f/64.f);
        float var = tot2 * (1.f/64.f) - mu*mu;
        zA = (a2A - mu) * rsqrtf(var + 1e-6f) * nsv + nbv;
        dstf[rowA*64 + c] = zA;
    }
    {
        float tot  = sRed[qB][0][0] + sRed[qB][1][0];
        float tot2 = sRed[qB][0][1] + sRed[qB][1][1];
        float mu = tot * (1.f/64.f);
        float var = tot2 * (1.f/64.f) - mu*mu;
        zB = (a2B - mu) * rsqrtf(var + 1e-6f) * nsv + nbv;
        dstf[rowB*64 + c] = zB;
    }
    if (iblk == 5) return;

    __syncthreads();          // residual reads of sy done before overwrite
    sy[qA][c] = zA;
    sy[qB][c] = zB;
    __syncthreads();

    // ---- next-block projections into buffer (iblk+1)&1 ----
    const int buf2 = ((iblk + 1) & 1) * NB;
    const int nblk = iblk + 1;
    const int g2 = tid >> 6;              // 0..3 -> rows {2*g2, 2*g2+1}
    const int r0q = g2*2;
    const int rowP = b*LL + blockIdx.x*8 + r0q;
    if (side == 0) {
        const float* W = wq + nblk*4096;
        float pa = bq[nblk*64 + c], pb = pa;
#pragma unroll 16
        for (int k = 0; k < 64; ++k) {
            float w = W[k*64 + c];
            pa = fmaf(sy[r0q][k],     w, pa);
            pb = fmaf(sy[r0q + 1][k], w, pb);
        }
        g_q1[buf2 + rowP*64 + c]       = pa;
        g_q1[buf2 + (rowP + 1)*64 + c] = pb;
    } else {
        const float* Wm[3] = { wq + nblk*4096, wk + nblk*4096, wv + nblk*4096 };
        const float* Bm[3] = { bq + nblk*64, bk + nblk*64, bv + nblk*64 };
        float* Dm[3] = { g_q2 + buf2, g_kk + buf2, g_vv + buf2 };
#pragma unroll
        for (int mm = 0; mm < 3; ++mm) {
            const float* W = Wm[mm];
            float pa = Bm[mm][c], pb = pa;
#pragma unroll 16
            for (int k = 0; k < 64; ++k) {
                float w = W[k*64 + c];
                pa = fmaf(sy[r0q][k],     w, pa);
                pb = fmaf(sy[r0q + 1][k], w, pb);
            }
            Dm[mm][rowP*64 + c]       = pa;
            Dm[mm][(rowP + 1)*64 + c] = pb;
        }
    }
}

// ---------------------------------------------------------------------------
// Head: final LN + MLP 64->128 relu ->2.  out = [mu(2048) | std(2048)]
// ---------------------------------------------------------------------------
__global__ __launch_bounds__(128) void head_kernel(
    const float* __restrict__ fns, const float* __restrict__ fnb,
    const float* __restrict__ hw1, const float* __restrict__ hb1,
    const float* __restrict__ hw2, const float* __restrict__ hb2,
    float* __restrict__ out)
{
    __shared__ float sx[64], sh[128], sp0[128], sp1[128], sred[2];
    int row = blockIdx.x, tid = threadIdx.x;
    if (tid < 64) sx[tid] = g_qvs[row*64 + tid];
    __syncthreads();
    if (tid < 32) {
        float v0 = sx[tid], v1 = sx[tid + 32];
        float s = v0 + v1;
#pragma unroll
        for (int off = 16; off; off >>= 1)
            s += __shfl_xor_sync(0xffffffffu, s, off);
        float mu = s * (1.f/64.f);
        float e0 = v0 - mu, e1 = v1 - mu;
        float qv = fmaf(e0, e0, e1*e1);
#pragma unroll
        for (int off = 16; off; off >>= 1)
            qv += __shfl_xor_sync(0xffffffffu, qv, off);
        if (tid == 0) { sred[0] = mu; sred[1] = rsqrtf(qv*(1.f/64.f) + 1e-6f); }
    }
    __syncthreads();
    if (tid < 64) sx[tid] = (sx[tid] - sred[0]) * sred[1] * fns[tid] + fnb[tid];
    __syncthreads();
    float acc = hb1[tid];
#pragma unroll 16
    for (int k = 0; k < 64; ++k) acc = fmaf(sx[k], hw1[k*128 + tid], acc);
    sh[tid] = fmaxf(acc, 0.f);
    __syncthreads();
    sp0[tid] = sh[tid] * hw2[tid*2 + 0];
    sp1[tid] = sh[tid] * hw2[tid*2 + 1];
    __syncthreads();
    for (int s = 64; s > 0; s >>= 1) {
        if (tid < s) { sp0[tid] += sp0[tid + s]; sp1[tid] += sp1[tid + s]; }
        __syncthreads();
    }
    if (tid == 0) {
        out[row]        = sp0[0] + hb2[0];
        out[2048 + row] = __expf(0.5f * (sp1[0] + hb2[1]));
    }
}

// ---------------------------------------------------------------------------
extern "C" void kernel_launch(void* const* d_in, const int* in_sizes, int n_in,
                              void* d_out, int out_size)
{
    const float* s_ctx   = (const float*)d_in[0];
    const float* f_ctx   = (const float*)d_in[1];
    const float* s_test  = (const float*)d_in[2];
    const float* table   = (const float*)d_in[3];
    const float* emb_w1  = (const float*)d_in[4];
    const float* emb_b1  = (const float*)d_in[5];
    const float* emb_w2  = (const float*)d_in[6];
    const float* emb_b2  = (const float*)d_in[7];
    const float* attn_wq = (const float*)d_in[8];
    const float* attn_bq = (const float*)d_in[9];
    const float* attn_wk = (const float*)d_in[10];
    const float* attn_bk = (const float*)d_in[11];
    const float* attn_wv = (const float*)d_in[12];
    const float* attn_bv = (const float*)d_in[13];
    const float* attn_wo = (const float*)d_in[14];
    const float* attn_bo = (const float*)d_in[15];
    const float* ffn_w1  = (const float*)d_in[16];
    const float* ffn_b1  = (const float*)d_in[17];
    const float* ffn_w2  = (const float*)d_in[18];
    const float* ffn_b2  = (const float*)d_in[19];
    const float* bias_w1 = (const float*)d_in[20];
    const float* bias_b1 = (const float*)d_in[21];
    const float* bias_w2 = (const float*)d_in[22];
    const float* bias_b2 = (const float*)d_in[23];
    const float* norm_s  = (const float*)d_in[24];
    const float* norm_b  = (const float*)d_in[25];
    const float* fnorm_s = (const float*)d_in[26];
    const float* fnorm_b = (const float*)d_in[27];
    const float* head_w1 = (const float*)d_in[28];
    const float* head_b1 = (const float*)d_in[29];
    const float* head_w2 = (const float*)d_in[30];
    const float* head_b2 = (const float*)d_in[31];

    static int attr_done = 0;
    if (!attr_done) {
        cudaFuncSetAttribute(attn_kernel,
            cudaFuncAttributeMaxDynamicSharedMemorySize, 65536);
        attr_done = 1;
    }

    bias_setup_kernel<<<6, 32>>>(bias_w1, bias_b1, bias_w2, bias_b2);
    dist_kernel<<<dim3(128, BB, 2), 256>>>(s_test, s_ctx);
    embed_kernel<<<1024, 256>>>(s_ctx, f_ctx, s_test, table,
                                emb_w1, emb_b1, emb_w2, emb_b2,
                                attn_wq, attn_bq, attn_wk, attn_bk,
                                attn_wv, attn_bv);
    for (int i = 0; i < 6; ++i) {
        attn_kernel<<<dim3(128, BB, 2), 256, 65536>>>(
            i, attn_wo, attn_bo, norm_s, norm_b,
            ffn_w1, ffn_b1, ffn_w2, ffn_b2,
            attn_wq, attn_bq, attn_wk, attn_bk, attn_wv, attn_bv);
    }
    head_kernel<<<2048, 128>>>(fnorm_s, fnorm_b, head_w1, head_b1,
                               head_w2, head_b2, (float*)d_out);
}

// round 17
// speedup vs baseline: 1.0187x; 1.0187x over previous
#include <cuda_runtime.h>

#define BB 2
#define LL 1024
#define DD 64
#define NROWS (BB*LL)
#define SCALE 0.35355339059327373f
#define LOG2E 1.4426950408889634f
#define SCALE2 (SCALE * LOG2E)

// persistent activations (no allocation allowed)
__device__ float g_qvs[NROWS*DD];
__device__ float g_kvs[NROWS*DD];
__device__ float g_attq[NROWS*DD];
__device__ float g_attk[NROWS*DD];
__device__ float g_q1[NROWS*DD];
__device__ float g_q2[NROWS*DD];
__device__ float g_kk[NROWS*DD];
__device__ float g_vv[NROWS*DD];

// precomputed squared distances, tiled to match attn staging:
// [side][b][qtile(128)][ktile(16)][qi(8)*64 + k(64)]  = 16 MB
__device__ float g_dist[2][BB][128][16][512];

// piecewise-linear distance-bias tables (per block), pre-scaled by log2(e)
__device__ float g_pl_t[6][16];
__device__ float g_pl_AC[6][17][16];
__device__ int   g_pl_i0[6];

__device__ __forceinline__ float ex2f(float x) {
    float r; asm("ex2.approx.f32 %0, %1;" : "=f"(r) : "f"(x)); return r;
}
__device__ __forceinline__ unsigned smem_u32(const void* p) {
    return (unsigned)__cvta_generic_to_shared(p);
}
__device__ __forceinline__ void cpa16(unsigned dst, const void* src) {
    asm volatile("cp.async.cg.shared.global [%0], [%1], 16;" :: "r"(dst), "l"(src));
}

// ---------------------------------------------------------------------------
// Setup: fold dist-bias MLP into 17-interval piecewise-linear form (x log2e).
// ---------------------------------------------------------------------------
__global__ void bias_setup_kernel(
    const float* __restrict__ bw1, const float* __restrict__ bb1,
    const float* __restrict__ bw2, const float* __restrict__ bb2)
{
    int i = blockIdx.x;
    if (threadIdx.x != 0) return;
    float w1[16], b1[16], t[16];
    for (int j = 0; j < 16; ++j) {
        w1[j] = bw1[i*16 + j];
        b1[j] = bb1[i*16 + j];
        t[j]  = (w1[j] != 0.f) ? (-b1[j] / w1[j]) : -1e30f;
    }
    int ord[16];
    for (int j = 0; j < 16; ++j) ord[j] = j;
    for (int a = 1; a < 16; ++a) {
        int o = ord[a]; float tv = t[o]; int b = a - 1;
        while (b >= 0 && t[ord[b]] > tv) { ord[b+1] = ord[b]; --b; }
        ord[b+1] = o;
    }
    int i0 = 0;
    for (int j = 0; j < 16; ++j) {
        g_pl_t[i][j] = t[ord[j]];
        if (t[ord[j]] <= 0.f) ++i0;
    }
    g_pl_i0[i] = i0;
    for (int m = 0; m <= 16; ++m) {
        float A[8], C[8];
        for (int h = 0; h < 8; ++h) { A[h] = 0.f; C[h] = 0.f; }
        for (int a = 0; a < 16; ++a) {
            int j = ord[a];
            bool act;
            if (w1[j] > 0.f)      act = (a < m);
            else if (w1[j] < 0.f) act = (a >= m);
            else                  act = (b1[j] > 0.f);
            if (act) {
                for (int h = 0; h < 8; ++h) {
                    A[h] += w1[j] * bw2[i*128 + j*8 + h];
                    C[h] += b1[j] * bw2[i*128 + j*8 + h];
                }
            }
        }
        for (int h = 0; h < 8; ++h) {
            g_pl_AC[i][m][h]     = A[h] * LOG2E;
            g_pl_AC[i][m][8 + h] = (C[h] + bb2[i*8 + h]) * LOG2E;
        }
    }
}

// ---------------------------------------------------------------------------
// Distance precompute: d(q,k) once, reused across all 6 blocks.
// ---------------------------------------------------------------------------
__global__ __launch_bounds__(256) void dist_kernel(
    const float* __restrict__ s_test, const float* __restrict__ s_ctx)
{
    __shared__ float2 sq[8];
    int tid = threadIdx.x;
    int qt = blockIdx.x, b = blockIdx.y, side = blockIdx.z;
    const float2* qc = (const float2*)(side ? s_ctx : s_test) + b*LL + qt*8;
    const float2* kc = (const float2*)s_ctx + b*LL;
    if (tid < 8) sq[tid] = qc[tid];
    __syncthreads();
    int qi = tid >> 5, lane = tid & 31;
    float qx = sq[qi].x, qy = sq[qi].y;
    float* D = &g_dist[side][b][qt][0][0];
#pragma unroll 4
    for (int kt = 0; kt < 16; ++kt) {
#pragma unroll
        for (int kk = 0; kk < 2; ++kk) {
            int k = kt*64 + kk*32 + lane;
            float2 c = kc[k];
            float dx = qx - c.x, dy = qy - c.y;
            D[kt*512 + qi*64 + kk*32 + lane] = fmaf(dx, dx, dy*dy);
        }
    }
}

// ---------------------------------------------------------------------------
// Embed: 4 rows/CTA + fused block-0 projections.
// ---------------------------------------------------------------------------
__global__ __launch_bounds__(256) void embed_kernel(
    const float* __restrict__ s_ctx, const float* __restrict__ f_ctx,
    const float* __restrict__ s_test, const float* __restrict__ table,
    const float* __restrict__ w1, const float* __restrict__ b1,
    const float* __restrict__ w2, const float* __restrict__ b2,
    const float* __restrict__ wq, const float* __restrict__ bq,
    const float* __restrict__ wk, const float* __restrict__ bk,
    const float* __restrict__ wv, const float* __restrict__ bv)
{
    __shared__ float xs[4][8];
    __shared__ float h4[4][256];
    __shared__ float part[4][256];
    __shared__ float sy[4][64];
    int tid = threadIdx.x;
    int row0 = blockIdx.x * 4;
    int sideq = row0 >> 11;
    if (tid < 32) {
        int r = tid >> 3, i = tid & 7;
        if (i < 7) {
            int row = (row0 + r) & 2047;
            int b = row >> 10, pos = row & 1023;
            float v;
            if (sideq == 0) {
                v = (i < 4) ? table[4 + i]
                  : (i < 6) ? s_ctx[(b*LL + pos)*2 + i - 4]
                            : f_ctx[b*LL + pos];
            } else {
                v = (i < 4) ? table[i]
                  : (i < 6) ? s_test[(b*LL + pos)*2 + i - 4]
                            : 0.f;
            }
            xs[r][i] = v;
        }
    }
    __syncthreads();
    float b1v = b1[tid];
    float a0 = b1v, a1 = b1v, a2 = b1v, a3 = b1v;
#pragma unroll
    for (int i = 0; i < 7; ++i) {
        float w = w1[i*256 + tid];
        a0 = fmaf(xs[0][i], w, a0);
        a1 = fmaf(xs[1][i], w, a1);
        a2 = fmaf(xs[2][i], w, a2);
        a3 = fmaf(xs[3][i], w, a3);
    }
    h4[0][tid] = fmaxf(a0, 0.f); h4[1][tid] = fmaxf(a1, 0.f);
    h4[2][tid] = fmaxf(a2, 0.f); h4[3][tid] = fmaxf(a3, 0.f);
    __syncthreads();
    int oc = tid & 63, g = tid >> 6;
    float p0 = 0.f, p1 = 0.f, p2 = 0.f, p3 = 0.f;
#pragma unroll 8
    for (int j = g*64; j < g*64 + 64; ++j) {
        float w = w2[j*64 + oc];
        p0 = fmaf(h4[0][j], w, p0);
        p1 = fmaf(h4[1][j], w, p1);
        p2 = fmaf(h4[2][j], w, p2);
        p3 = fmaf(h4[3][j], w, p3);
    }
    part[0][tid] = p0; part[1][tid] = p1; part[2][tid] = p2; part[3][tid] = p3;
    __syncthreads();
    {
        int r = tid >> 6, col = tid & 63;
        float v = part[r][col] + part[r][64 + col] + part[r][128 + col]
                + part[r][192 + col] + b2[col];
        int rr = (row0 + r) & 2047;
        float* dst = sideq ? g_qvs : g_kvs;
        dst[rr*64 + col] = v;
        sy[r][col] = v;
    }
    __syncthreads();

    // fused block-0 projections from sy
    {
        int r = tid >> 6, c = tid & 63;
        int rr = (row0 + r) & 2047;
        const float* Wm[3]; const float* Bm[3]; float* Dm[3]; int nmat;
        if (sideq == 0) {
            nmat = 3;
            Wm[0] = wq; Bm[0] = bq; Dm[0] = g_q2;
            Wm[1] = wk; Bm[1] = bk; Dm[1] = g_kk;
            Wm[2] = wv; Bm[2] = bv; Dm[2] = g_vv;
        } else {
            nmat = 1;
            Wm[0] = wq; Bm[0] = bq; Dm[0] = g_q1;
        }
        for (int mm = 0; mm < nmat; ++mm) {
            const float* W = Wm[mm];
            float pa = Bm[mm][c];
#pragma unroll 16
            for (int k = 0; k < 64; ++k)
                pa = fmaf(sy[r][k], W[k*64 + c], pa);
            Dm[mm][rr*64 + c] = pa;
        }
    }
}

// ---------------------------------------------------------------------------
// Fused biased attention + out-proj + residual + LN.  (R15 best config)
// grid (128, B, 2). CTA = 8 warps = 8 queries. Warp w = head w, ALL 8 queries.
// Distances precomputed (g_dist) and cp.async-staged with K/V.
// ---------------------------------------------------------------------------
__global__ __launch_bounds__(256, 2) void attn_kernel(
    int iblk,
    const float* __restrict__ wo, const float* __restrict__ bo,
    const float* __restrict__ ns, const float* __restrict__ nb)
{
    // dynamic: K0[1024] V0[1024] K1[1024] V1[1024] float4 (64KB)
    extern __shared__ float4 dyn[];

    __shared__ float  sQ[512];       // 8 queries x 64, pre-scaled
    __shared__ float  sDbuf[2][512]; // double-buffered distance tiles
    __shared__ float  sAC[272];      // PL tables
    __shared__ float  sO[512];
    __shared__ float  sRed[8][2][2];

    const int tid = threadIdx.x, wid = tid >> 5, lane = tid & 31;
    const int side = blockIdx.z, b = blockIdx.y;

    const float* Qp = side ? g_q2 : g_q1;

    for (int n = tid; n < 272; n += 256)
        sAC[n] = ((const float*)g_pl_AC)[iblk*272 + n];
    sQ[tid]       = Qp[(b*LL + blockIdx.x*8)*64 + tid] * SCALE2;
    sQ[256 + tid] = Qp[(b*LL + blockIdx.x*8)*64 + 256 + tid] * SCALE2;

    const int i0 = g_pl_i0[iblk];
    const float* trg = g_pl_t[iblk];

    float l[8];
#pragma unroll
    for (int i = 0; i < 8; ++i) l[i] = 0.f;
    float o[64];
#pragma unroll
    for (int d = 0; d < 64; ++d) o[d] = 0.f;

    const int ksw = lane & 15, kb0 = lane << 4;
    const int ikk0 = kb0 + ((2*wid)     ^ ksw);
    const int ikk1 = kb0 + ((2*wid + 1) ^ ksw);

    const float4* Kg = (const float4*)(g_kk + b*LL*64);
    const float4* Vg = (const float4*)(g_vv + b*LL*64);
    const float4* Dg = (const float4*)&g_dist[side][b][blockIdx.x][0][0];

    int sgN[4]; unsigned sgU[4];
#pragma unroll
    for (int n4 = 0; n4 < 4; ++n4) {
        int n = n4*256 + tid;
        int kr = n >> 4, c = n & 15;
        sgN[n4] = n;
        sgU[n4] = (unsigned)(((kr << 4) + (c ^ (kr & 15))) * 16);
    }
    const unsigned uK0 = smem_u32(dyn);
    const unsigned uV0 = uK0 + 16384;
    const unsigned uK1 = uK0 + 32768;
    const unsigned uV1 = uK0 + 49152;
    const unsigned uD0 = smem_u32(sDbuf);
    const unsigned uD1 = uD0 + 2048;

    __syncthreads();   // sQ / sAC visible
    const float A16 = sAC[256 + wid];
    const float C16 = sAC[264 + wid];
    const float4* sQ4 = (const float4*)sQ;

    // prologue: stage tile 0 into buffer 0 (K, V, D)
#pragma unroll
    for (int n4 = 0; n4 < 4; ++n4) {
        cpa16(uK0 + sgU[n4], Kg + sgN[n4]);
        cpa16(uV0 + sgU[n4], Vg + sgN[n4]);
    }
    if (tid < 128) cpa16(uD0 + tid*16, Dg + tid);
    asm volatile("cp.async.commit_group;");

    for (int t = 0; t < 16; ++t) {
        const int bf = t & 1;
        asm volatile("cp.async.wait_group 0;");
        __syncthreads();   // tile t visible; all warps done with tile t-1

        if (t + 1 < 16) {
            const unsigned uK = bf ? uK0 : uK1;
            const unsigned uV = bf ? uV0 : uV1;
            const unsigned uD = bf ? uD0 : uD1;
#pragma unroll
            for (int n4 = 0; n4 < 4; ++n4) {
                cpa16(uK + sgU[n4], Kg + (t+1)*1024 + sgN[n4]);
                cpa16(uV + sgU[n4], Vg + (t+1)*1024 + sgN[n4]);
            }
            if (tid < 128) cpa16(uD + tid*16, Dg + (t+1)*128 + tid);
            asm volatile("cp.async.commit_group;");
        }

        const float4* sK = bf ? (dyn + 2048) : dyn;
        const float4* sV = bf ? (dyn + 3072) : (dyn + 1024);
        const float*  sD = sDbuf[bf];

        // scores from PL bias (distances pre-staged)
        float s[16];
        if (i0 == 16) {
#pragma unroll
            for (int qi = 0; qi < 8; ++qi) {
                float dq0 = sD[qi*64 + lane];
                float dq1 = sD[qi*64 + 32 + lane];
                s[qi*2+0] = fmaf(A16, dq0, C16);
                s[qi*2+1] = fmaf(A16, dq1, C16);
            }
        } else {
#pragma unroll
            for (int qi = 0; qi < 8; ++qi) {
                float dq0 = sD[qi*64 + lane];
                float dq1 = sD[qi*64 + 32 + lane];
                int m0 = i0, m1 = i0;
                for (int i = i0; i < 16; ++i) {
                    float tv = trg[i];
                    m0 += dq0 > tv; m1 += dq1 > tv;
                }
                s[qi*2+0] = fmaf(sAC[m0*16 + wid], dq0, sAC[m0*16 + 8 + wid]);
                s[qi*2+1] = fmaf(sAC[m1*16 + wid], dq1, sAC[m1*16 + 8 + wid]);
            }
        }

        // QK dots: each K load feeds 8 queries
#pragma unroll
        for (int cc = 0; cc < 2; ++cc) {
            const int ik = cc ? ikk1 : ikk0;
            float4 k0 = sK[ik];
            float4 k1 = sK[ik + 512];
#pragma unroll
            for (int qi = 0; qi < 8; ++qi) {
                float4 qv = sQ4[qi*16 + 2*wid + cc];
                s[qi*2]   = fmaf(qv.x, k0.x, s[qi*2]);
                s[qi*2]   = fmaf(qv.y, k0.y, s[qi*2]);
                s[qi*2]   = fmaf(qv.z, k0.z, s[qi*2]);
                s[qi*2]   = fmaf(qv.w, k0.w, s[qi*2]);
                s[qi*2+1] = fmaf(qv.x, k1.x, s[qi*2+1]);
                s[qi*2+1] = fmaf(qv.y, k1.y, s[qi*2+1]);
                s[qi*2+1] = fmaf(qv.z, k1.z, s[qi*2+1]);
                s[qi*2+1] = fmaf(qv.w, k1.w, s[qi*2+1]);
            }
        }

        // exp in place; accumulate l
#pragma unroll
        for (int i = 0; i < 16; ++i) s[i] = ex2f(s[i]);
#pragma unroll
        for (int qi = 0; qi < 8; ++qi) l[qi] += s[qi*2] + s[qi*2+1];

        // V accumulation: each V load feeds 8 queries
#pragma unroll
        for (int cc = 0; cc < 2; ++cc) {
            const int ik = cc ? ikk1 : ikk0;
            float4 v0 = sV[ik];
            float4 v1 = sV[ik + 512];
#pragma unroll
            for (int qi = 0; qi < 8; ++qi) {
                const int ob = qi*8 + cc*4;
                float pa = s[qi*2], pb = s[qi*2+1];
                o[ob+0] = fmaf(pa, v0.x, o[ob+0]);
                o[ob+0] = fmaf(pb, v1.x, o[ob+0]);
                o[ob+1] = fmaf(pa, v0.y, o[ob+1]);
                o[ob+1] = fmaf(pb, v1.y, o[ob+1]);
                o[ob+2] = fmaf(pa, v0.z, o[ob+2]);
                o[ob+2] = fmaf(pb, v1.z, o[ob+2]);
                o[ob+3] = fmaf(pa, v0.w, o[ob+3]);
                o[ob+3] = fmaf(pb, v1.w, o[ob+3]);
            }
        }
    }

    // merge lanes (butterfly)
#pragma unroll
    for (int i = 0; i < 8; ++i) {
        float lh = l[i];
#pragma unroll
        for (int off = 16; off; off >>= 1)
            lh += __shfl_xor_sync(0xffffffffu, lh, off);
        l[i] = 1.f / lh;
    }
#pragma unroll
    for (int d = 0; d < 64; ++d) {
        float v = o[d];
#pragma unroll
        for (int off = 16; off; off >>= 1)
            v += __shfl_xor_sync(0xffffffffu, v, off);
        o[d] = v * l[d >> 3];
    }

    // lane i extracts o[i], o[32+i]
    float mv0 = 0.f, mv1 = 0.f;
#pragma unroll
    for (int i = 0; i < 32; ++i)
        if (lane == i) { mv0 = o[i]; mv1 = o[32 + i]; }

    __syncthreads();   // all warps done with last tile K/V before Wo staging
    sO[(lane >> 3)*64       + wid*8 + (lane & 7)] = mv0;
    sO[(4 + (lane >> 3))*64 + wid*8 + (lane & 7)] = mv1;
    float* sWo = (float*)dyn;
    const float* Wog = wo + iblk*4096;
    for (int n = tid; n < 4096; n += 256) sWo[n] = Wog[n];
    __syncthreads();

    // out-proj + residual + LN: queries qA = tid>>6 and qB = qA+4
    const int c = tid & 63, qA = tid >> 6, qB = qA + 4;
    const int rowA = b*LL + blockIdx.x*8 + qA;
    const int rowB = rowA + 4;
    float accA = bo[iblk*64 + c], accB = accA;
#pragma unroll 16
    for (int i = 0; i < 64; ++i) {
        float w = sWo[i*64 + c];
        accA = fmaf(sO[qA*64 + i], w, accA);
        accB = fmaf(sO[qB*64 + i], w, accB);
    }
    const float* src = side ? g_kvs : g_qvs;
    accA += src[rowA*64 + c];
    accB += src[rowB*64 + c];

    float s1A = accA, s2A = accA*accA, s1B = accB, s2B = accB*accB;
#pragma unroll
    for (int off = 16; off; off >>= 1) {
        s1A += __shfl_xor_sync(0xffffffffu, s1A, off);
        s2A += __shfl_xor_sync(0xffffffffu, s2A, off);
        s1B += __shfl_xor_sync(0xffffffffu, s1B, off);
        s2B += __shfl_xor_sync(0xffffffffu, s2B, off);
    }
    const int half = (tid >> 5) & 1;
    if (lane == 0) {
        sRed[qA][half][0] = s1A; sRed[qA][half][1] = s2A;
        sRed[qB][half][0] = s1B; sRed[qB][half][1] = s2B;
    }
    __syncthreads();
    float* outp = side ? g_attk : g_attq;
    const float nsv = ns[iblk*64 + c], nbv = nb[iblk*64 + c];
    {
        float tot  = sRed[qA][0][0] + sRed[qA][1][0];
        float tot2 = sRed[qA][0][1] + sRed[qA][1][1];
        float mu = tot * (1.f/64.f);
        float var = tot2 * (1.f/64.f) - mu*mu;
        float rstd = rsqrtf(var + 1e-6f);
        outp[rowA*64 + c] = (accA - mu) * rstd * nsv + nbv;
    }
    {
        float tot  = sRed[qB][0][0] + sRed[qB][1][0];
        float tot2 = sRed[qB][0][1] + sRed[qB][1][1];
        float mu = tot * (1.f/64.f);
        float var = tot2 * (1.f/64.f) - mu*mu;
        float rstd = rsqrtf(var + 1e-6f);
        outp[rowB*64 + c] = (accB - mu) * rstd * nsv + nbv;
    }
}

// ---------------------------------------------------------------------------
// FFN + residual + LN + next-block projections.  (R15 config)
// 16 rows/CTA, 256 threads, grid 256; weights cp.async-staged once per CTA.
// ---------------------------------------------------------------------------
__global__ __launch_bounds__(256) void ffnproj_kernel(
    int iblk, int nblk,
    const float* __restrict__ fw1, const float* __restrict__ fb1,
    const float* __restrict__ fw2, const float* __restrict__ fb2,
    const float* __restrict__ ns, const float* __restrict__ nb,
    const float* __restrict__ wq, const float* __restrict__ bq,
    const float* __restrict__ wk, const float* __restrict__ bk,
    const float* __restrict__ wv, const float* __restrict__ bv)
{
    extern __shared__ float wsm[];   // [0..8191] W1, [8192..16383] W2 (64KB)
    __shared__ float sx[16][64];
    __shared__ float sh[16][128];
    __shared__ float sy[16][64];
    __shared__ float sred[16][2][2];

    int tid = threadIdx.x;
    int row0 = blockIdx.x * 16;
    int side = row0 >> 11;
    int r0 = row0 & 2047;
    const float* src = side ? g_attk : g_attq;
    float* dst = side ? g_kvs : g_qvs;

    {
        const float* W1g = fw1 + iblk*8192;
        const float* W2g = fw2 + iblk*8192;
        unsigned uw = smem_u32(wsm);
#pragma unroll
        for (int n = 0; n < 8; ++n) {
            int idx = n*1024 + tid*4;
            cpa16(uw + idx*4, W1g + idx);
            cpa16(uw + 32768 + idx*4, W2g + idx);
        }
        asm volatile("cp.async.commit_group;");
    }
    for (int n = tid; n < 1024; n += 256) sx[n >> 6][n & 63] = src[r0*64 + n];
    asm volatile("cp.async.wait_group 0;");
    __syncthreads();

    {
        int h = tid & 127, rg = tid >> 7;
        float b1v = fb1[iblk*128 + h];
        float acc[8];
#pragma unroll
        for (int r = 0; r < 8; ++r) acc[r] = b1v;
#pragma unroll 16
        for (int k = 0; k < 64; ++k) {
            float w = wsm[k*128 + h];
#pragma unroll
            for (int r = 0; r < 8; ++r) acc[r] = fmaf(sx[rg*8 + r][k], w, acc[r]);
        }
#pragma unroll
        for (int r = 0; r < 8; ++r) sh[rg*8 + r][h] = fmaxf(acc[r], 0.f);
    }
    __syncthreads();

    const float* W2s = wsm + 8192;
    int c = tid & 63, g2 = tid >> 6;
    float b2v = fb2[iblk*64 + c];
    float a2[4];
#pragma unroll
    for (int r = 0; r < 4; ++r) a2[r] = b2v;
#pragma unroll 16
    for (int k = 0; k < 128; ++k) {
        float w = W2s[k*64 + c];
#pragma unroll
        for (int r = 0; r < 4; ++r) a2[r] = fmaf(sh[g2*4 + r][k], w, a2[r]);
    }
#pragma unroll
    for (int r = 0; r < 4; ++r) a2[r] += sx[g2*4 + r][c];

    float s1[4], s2[4];
#pragma unroll
    for (int r = 0; r < 4; ++r) { s1[r] = a2[r]; s2[r] = a2[r]*a2[r]; }
#pragma unroll
    for (int off = 16; off; off >>= 1) {
#pragma unroll
        for (int r = 0; r < 4; ++r) {
            s1[r] += __shfl_xor_sync(0xffffffffu, s1[r], off);
            s2[r] += __shfl_xor_sync(0xffffffffu, s2[r], off);
        }
    }
    int lane = tid & 31, half = (tid >> 5) & 1;
    if (lane == 0) {
#pragma unroll
        for (int r = 0; r < 4; ++r) {
            sred[g2*4 + r][half][0] = s1[r];
            sred[g2*4 + r][half][1] = s2[r];
        }
    }
    __syncthreads();
    float nsv = ns[iblk*64 + c], nbv = nb[iblk*64 + c];
#pragma unroll
    for (int r = 0; r < 4; ++r) {
        int rr = g2*4 + r;
        float tot  = sred[rr][0][0] + sred[rr][1][0];
        float tot2 = sred[rr][0][1] + sred[rr][1][1];
        float mu = tot * (1.f/64.f);
        float var = tot2 * (1.f/64.f) - mu*mu;
        float rstd = rsqrtf(var + 1e-6f);
        float y = (a2[r] - mu) * rstd * nsv + nbv;
        sy[rr][c] = y;
        dst[(r0 + rr)*64 + c] = y;
    }
    __syncthreads();

    if (nblk < 0) return;

    const float* Wm[3]; const float* Bm[3]; float* Dm[3]; int nmat;
    if (side == 0) {
        nmat = 1;
        Wm[0] = wq + nblk*4096; Bm[0] = bq + nblk*64; Dm[0] = g_q1;
    } else {
        nmat = 3;
        Wm[0] = wq + nblk*4096; Bm[0] = bq + nblk*64; Dm[0] = g_q2;
        Wm[1] = wk + nblk*4096; Bm[1] = bk + nblk*64; Dm[1] = g_kk;
        Wm[2] = wv + nblk*4096; Bm[2] = bv + nblk*64; Dm[2] = g_vv;
    }
    for (int mm = 0; mm < nmat; ++mm) {
        const float* W = Wm[mm];
        float bv = Bm[mm][c];
        float pa[4];
#pragma unroll
        for (int r = 0; r < 4; ++r) pa[r] = bv;
#pragma unroll 16
        for (int k = 0; k < 64; ++k) {
            float w = W[k*64 + c];
#pragma unroll
            for (int r = 0; r < 4; ++r) pa[r] = fmaf(sy[g2*4 + r][k], w, pa[r]);
        }
#pragma unroll
        for (int r = 0; r < 4; ++r) Dm[mm][(r0 + g2*4 + r)*64 + c] = pa[r];
    }
}

// ---------------------------------------------------------------------------
// Head (batched): 8 rows/CTA, 256 thr, grid 256.
// final LN + MLP 64->128 relu ->2. out = [mu(2048) | std(2048)]
// ---------------------------------------------------------------------------
__global__ __launch_bounds__(256) void head_kernel(
    const float* __restrict__ fns, const float* __restrict__ fnb,
    const float* __restrict__ hw1, const float* __restrict__ hb1,
    const float* __restrict__ hw2, const float* __restrict__ hb2,
    float* __restrict__ out)
{
    __shared__ float sx[8][64];
    __shared__ float sh[8][128];
    __shared__ float sred[8][2][2];
    int tid = threadIdx.x;
    int row0 = blockIdx.x * 8;

    for (int n = tid; n < 512; n += 256) sx[n >> 6][n & 63] = g_qvs[row0*64 + n];
    __syncthreads();

    // final LN: rows qA = tid>>6, qB = qA+4 (col c = tid&63)
    const int c = tid & 63, qA = tid >> 6, qB = qA + 4;
    const int lane = tid & 31, half = (tid >> 5) & 1;
    float vA = sx[qA][c], vB = sx[qB][c];
    {
        float s1A = vA, s2A = vA*vA, s1B = vB, s2B = vB*vB;
#pragma unroll
        for (int off = 16; off; off >>= 1) {
            s1A += __shfl_xor_sync(0xffffffffu, s1A, off);
            s2A += __shfl_xor_sync(0xffffffffu, s2A, off);
            s1B += __shfl_xor_sync(0xffffffffu, s1B, off);
            s2B += __shfl_xor_sync(0xffffffffu, s2B, off);
        }
        if (lane == 0) {
            sred[qA][half][0] = s1A; sred[qA][half][1] = s2A;
            sred[qB][half][0] = s1B; sred[qB][half][1] = s2B;
        }
    }
    __syncthreads();
    {
        float tot  = sred[qA][0][0] + sred[qA][1][0];
        float tot2 = sred[qA][0][1] + sred[qA][1][1];
        float mu = tot * (1.f/64.f);
        float var = tot2 * (1.f/64.f) - mu*mu;
        sx[qA][c] = (vA - mu) * rsqrtf(var + 1e-6f) * fns[c] + fnb[c];
    }
    {
        float tot  = sred[qB][0][0] + sred[qB][1][0];
        float tot2 = sred[qB][0][1] + sred[qB][1][1];
        float mu = tot * (1.f/64.f);
        float var = tot2 * (1.f/64.f) - mu*mu;
        sx[qB][c] = (vB - mu) * rsqrtf(var + 1e-6f) * fns[c] + fnb[c];
    }
    __syncthreads();

    // hidden layer: h = tid&127, rg = tid>>7 handles 4 rows; w reused 4x
    {
        int h = tid & 127, rg = tid >> 7;
        float b1v = hb1[h];
        float acc[4];
#pragma unroll
        for (int r = 0; r < 4; ++r) acc[r] = b1v;
#pragma unroll 16
        for (int k = 0; k < 64; ++k) {
            float w = hw1[k*128 + h];
#pragma unroll
            for (int r = 0; r < 4; ++r) acc[r] = fmaf(sx[rg*4 + r][k], w, acc[r]);
        }
#pragma unroll
        for (int r = 0; r < 4; ++r) sh[rg*4 + r][h] = fmaxf(acc[r], 0.f);
    }
    __syncthreads();

    // output: warp w handles row w; lanes reduce 128 hidden for both outputs
    {
        int w = tid >> 5;
        float p0 = 0.f, p1 = 0.f;
#pragma unroll
        for (int i = 0; i < 4; ++i) {
            int k = lane + i*32;
            float hv = sh[w][k];
            p0 = fmaf(hv, hw2[k*2 + 0], p0);
            p1 = fmaf(hv, hw2[k*2 + 1], p1);
        }
#pragma unroll
        for (int off = 16; off; off >>= 1) {
            p0 += __shfl_xor_sync(0xffffffffu, p0, off);
            p1 += __shfl_xor_sync(0xffffffffu, p1, off);
        }
        if (lane == 0) {
            int row = row0 + w;
            out[row]        = p0 + hb2[0];
            out[2048 + row] = __expf(0.5f * (p1 + hb2[1]));
        }
    }
}

// ---------------------------------------------------------------------------
extern "C" void kernel_launch(void* const* d_in, const int* in_sizes, int n_in,
                              void* d_out, int out_size)
{
    const float* s_ctx   = (const float*)d_in[0];
    const float* f_ctx   = (const float*)d_in[1];
    const float* s_test  = (const float*)d_in[2];
    const float* table   = (const float*)d_in[3];
    const float* emb_w1  = (const float*)d_in[4];
    const float* emb_b1  = (const float*)d_in[5];
    const float* emb_w2  = (const float*)d_in[6];
    const float* emb_b2  = (const float*)d_in[7];
    const float* attn_wq = (const float*)d_in[8];
    const float* attn_bq = (const float*)d_in[9];
    const float* attn_wk = (const float*)d_in[10];
    const float* attn_bk = (const float*)d_in[11];
    const float* attn_wv = (const float*)d_in[12];
    const float* attn_bv = (const float*)d_in[13];
    const float* attn_wo = (const float*)d_in[14];
    const float* attn_bo = (const float*)d_in[15];
    const float* ffn_w1  = (const float*)d_in[16];
    const float* ffn_b1  = (const float*)d_in[17];
    const float* ffn_w2  = (const float*)d_in[18];
    const float* ffn_b2  = (const float*)d_in[19];
    const float* bias_w1 = (const float*)d_in[20];
    const float* bias_b1 = (const float*)d_in[21];
    const float* bias_w2 = (const float*)d_in[22];
    const float* bias_b2 = (const float*)d_in[23];
    const float* norm_s  = (const float*)d_in[24];
    const float* norm_b  = (const float*)d_in[25];
    const float* fnorm_s = (const float*)d_in[26];
    const float* fnorm_b = (const float*)d_in[27];
    const float* head_w1 = (const float*)d_in[28];
    const float* head_b1 = (const float*)d_in[29];
    const float* head_w2 = (const float*)d_in[30];
    const float* head_b2 = (const float*)d_in[31];

    static int attr_done = 0;
    if (!attr_done) {
        cudaFuncSetAttribute(attn_kernel,
            cudaFuncAttributeMaxDynamicSharedMemorySize, 65536);
        cudaFuncSetAttribute(ffnproj_kernel,
            cudaFuncAttributeMaxDynamicSharedMemorySize, 65536);
        attr_done = 1;
    }

    bias_setup_kernel<<<6, 32>>>(bias_w1, bias_b1, bias_w2, bias_b2);
    dist_kernel<<<dim3(128, BB, 2), 256>>>(s_test, s_ctx);
    embed_kernel<<<1024, 256>>>(s_ctx, f_ctx, s_test, table,
                                emb_w1, emb_b1, emb_w2, emb_b2,
                                attn_wq, attn_bq, attn_wk, attn_bk,
                                attn_wv, attn_bv);
    for (int i = 0; i < 6; ++i) {
        attn_kernel<<<dim3(128, BB, 2), 256, 65536>>>(i, attn_wo, attn_bo,
                                                      norm_s, norm_b);
        ffnproj_kernel<<<256, 256, 65536>>>(i, (i < 5) ? i + 1 : -1,
                                            ffn_w1, ffn_b1, ffn_w2, ffn_b2,
                                            norm_s, norm_b,
                                            attn_wq, attn_bq, attn_wk, attn_bk,
                                            attn_wv, attn_bv);
    }
    head_kernel<<<256, 256>>>(fnorm_s, fnorm_b, head_w1, head_b1,
                              head_w2, head_b2, (float*)d_out);
}